// round 7
// baseline (speedup 1.0000x reference)
#include <cuda_runtime.h>
#include <cstdint>

#define B_  64
#define T_  2048
#define I_  256
#define H_  256
#define G3_ 768

// 402 MB scratch for precomputed input gates: layout [t][b][768]
__device__ float g_Gi[(size_t)B_ * T_ * G3_];

// ======================= Phase 1: Gi = x @ W_ih^T + b_ih =======================
#define BM 128
#define BN 64
#define BK 32
#define PAD 36

__global__ __launch_bounds__(256) void gi_gemm(
    const float* __restrict__ x, const float* __restrict__ W_ih,
    const float* __restrict__ b_ih, const int* __restrict__ lengths)
{
    const int m0    = blockIdx.x * BM;        // row = b*T + t
    const int batch = m0 >> 11;               // 2048 rows per batch
    const int t0    = m0 & (T_ - 1);
    if (t0 >= __ldg(&lengths[batch])) return; // whole tile masked -> skip
    const int n0 = blockIdx.y * BN;

    __shared__ float As[BM][PAD];
    __shared__ float Bs[BN][PAD];

    const int tid = threadIdx.x;
    const int tx = tid & 15, ty = tid >> 4;   // 16 x 16 -> thread tile 8(m) x 4(n)

    float acc[8][4];
#pragma unroll
    for (int i = 0; i < 8; i++)
#pragma unroll
        for (int c = 0; c < 4; c++) acc[i][c] = 0.f;

    for (int kt = 0; kt < I_; kt += BK) {
#pragma unroll
        for (int j = 0; j < 4; j++) {
            int idx = tid + j * 256;
            int row = idx >> 3, kp = idx & 7;
            float4 v = *(const float4*)&x[(size_t)(m0 + row) * I_ + kt + kp * 4];
            *(float4*)&As[row][kp * 4] = v;
        }
#pragma unroll
        for (int j = 0; j < 2; j++) {
            int idx = tid + j * 256;
            int row = idx >> 3, kp = idx & 7;
            float4 v = *(const float4*)&W_ih[(size_t)(n0 + row) * I_ + kt + kp * 4];
            *(float4*)&Bs[row][kp * 4] = v;
        }
        __syncthreads();
#pragma unroll
        for (int k = 0; k < BK; k++) {
            float a[8], b[4];
#pragma unroll
            for (int i = 0; i < 8; i++) a[i] = As[ty * 8 + i][k];
#pragma unroll
            for (int c = 0; c < 4; c++) b[c] = Bs[tx * 4 + c][k];
#pragma unroll
            for (int i = 0; i < 8; i++)
#pragma unroll
                for (int c = 0; c < 4; c++) acc[i][c] += a[i] * b[c];
        }
        __syncthreads();
    }

#pragma unroll
    for (int i = 0; i < 8; i++) {
        int t = t0 + ty * 8 + i;
        int n = n0 + tx * 4;
        float4 v;
        v.x = acc[i][0] + b_ih[n + 0];
        v.y = acc[i][1] + b_ih[n + 1];
        v.z = acc[i][2] + b_ih[n + 2];
        v.w = acc[i][3] + b_ih[n + 3];
        *(float4*)&g_Gi[((size_t)t * B_ + batch) * G3_ + n] = v;
    }
}

// ======================= Phase 2: recurrence =======================
// 64 clusters of 2 CTAs, ONE batch per cluster (b = blockIdx.x >> 1).
// CTA rank r owns H-cols [r*128, r*128+128) for 3 gates = 384 local rows.
// Warp w: kq = w & 1 (128-wide k half), row = (w>>1)*32 + lane (0..383).
// Thread holds W[grow][kq*128 .. +128) in 64 f32x2 REGISTERS.
// h (1 batch x 256) replicated per CTA, double-buffered; exchange via
// st.async.b64 pair stores to BOTH CTAs, per-buffer mbar (tx = 1024 B =
// 2 src x 128 cols x 4 B). Tmax = lengths[b] exactly (no wasted steps).
// Minimal sync domain: max-of-2 jitter, 6-load reduce tail, cheap tanh.

#define REC_THREADS 768
#define EXP_TX 1024

__device__ __forceinline__ float sigm(float v) { return 1.f / (1.f + __expf(-v)); }
__device__ __forceinline__ float tanh_fast(float u) {
    // sign-safe, overflow-free: t = e^{-2|u|} in (0,1]
    const float t = __expf(-2.f * fabsf(u));
    const float m = (1.f - t) / (1.f + t);
    return copysignf(m, u);
}

__device__ __forceinline__ unsigned long long fma2(unsigned long long a,
                                                   unsigned long long b,
                                                   unsigned long long c) {
    unsigned long long d;
    asm("fma.rn.f32x2 %0, %1, %2, %3;" : "=l"(d) : "l"(a), "l"(b), "l"(c));
    return d;
}
__device__ __forceinline__ unsigned long long add2(unsigned long long a,
                                                   unsigned long long b) {
    unsigned long long d;
    asm("add.rn.f32x2 %0, %1, %2;" : "=l"(d) : "l"(a), "l"(b));
    return d;
}
__device__ __forceinline__ unsigned long long packf2(float lo, float hi) {
    unsigned long long d;
    asm("mov.b64 %0, {%1, %2};" : "=l"(d) : "f"(lo), "f"(hi));
    return d;
}
__device__ __forceinline__ float unpack_sum(unsigned long long v) {
    float lo, hi;
    asm("mov.b64 {%0, %1}, %2;" : "=f"(lo), "=f"(hi) : "l"(v));
    return lo + hi;
}
__device__ __forceinline__ void mbar_wait_cluster(uint32_t mbar, uint32_t parity) {
    uint32_t done;
    asm volatile(
        "{\n\t.reg .pred p;\n\t"
        "mbarrier.try_wait.parity.acquire.cluster.shared::cta.b64 p, [%1], %2;\n\t"
        "selp.b32 %0, 1, 0, p;\n\t}"
        : "=r"(done) : "r"(mbar), "r"(parity) : "memory");
    while (!done) {
        asm volatile(
            "{\n\t.reg .pred p;\n\t"
            "mbarrier.try_wait.parity.acquire.cluster.shared::cta.b64 p, [%1], %2, 0x989680;\n\t"
            "selp.b32 %0, 1, 0, p;\n\t}"
            : "=r"(done) : "r"(mbar), "r"(parity) : "memory");
    }
}

__global__ void __cluster_dims__(2, 1, 1) __launch_bounds__(REC_THREADS, 1)
gru_rec(const float* __restrict__ att, const int* __restrict__ lengths,
        const float* __restrict__ W_hh, const float* __restrict__ b_hh,
        float* __restrict__ out)
{
    __shared__ alignas(16) float hb[2][256];      // [buf][col]
    __shared__ float ghp[2][2][384];              // [buf][kq][local row]
    __shared__ alignas(8) unsigned long long mbar[2];

    uint32_t rank;
    asm("mov.u32 %0, %%cluster_ctarank;" : "=r"(rank));
    const int b = blockIdx.x >> 1;                // one batch per cluster

    const int tid  = threadIdx.x;
    const int warp = tid >> 5;
    const int lane = tid & 31;
    const int kq   = warp & 1;         // k half: [kq*128, kq*128+128)
    const int row  = (warp >> 1) * 32 + lane;     // local row 0..383
    const int g    = row >> 7;         // gate 0..2
    const int c    = row & 127;        // col within slice

    // ---- W row-chunk into registers: 64 f32x2 ----
    const int grow = g * 256 + (int)rank * 128 + c;
    unsigned long long wq[64];
#pragma unroll
    for (int i = 0; i < 32; i++) {
        float4 v = *(const float4*)&W_hh[(size_t)grow * H_ + kq * 128 + i * 4];
        wq[2 * i + 0] = packf2(v.x, v.y);
        wq[2 * i + 1] = packf2(v.z, v.w);
    }

    // ---- zero h buffer 0, init mbarriers ----
    if (tid < 256) hb[0][tid] = 0.f;
    if (tid < 2) {
        uint32_t m = (uint32_t)__cvta_generic_to_shared(&mbar[tid]);
        asm volatile("mbarrier.init.shared.b64 [%0], 1;" :: "r"(m) : "memory");
    }

    // ---- gate-thread constants (threads 0..127 handle col = rank*128+tid) ----
    const bool is_gate = (tid < 128);
    const int colg = (int)rank * 128 + tid;       // global col (gate threads)
    float bhr = 0.f, bhz = 0.f, bhn = 0.f;
    if (is_gate) {
        bhr = b_hh[colg];
        bhz = b_hh[256 + colg];
        bhn = b_hh[512 + colg];
    }
    float hreg = 0.f;                             // own h[col] across steps
    const int Tmax = __ldg(&lengths[b]);          // exact: same for both CTAs

    __syncthreads();
    asm volatile("barrier.cluster.arrive.aligned;" ::: "memory");
    asm volatile("barrier.cluster.wait.aligned;" ::: "memory");

    uint32_t ph0 = 0, ph1 = 0;

    for (int t = 0; t < Tmax; t++) {
        const int cur = t & 1, nxt = cur ^ 1;

        // arm the buffer written this step
        if (tid == 0) {
            uint32_t mn = (uint32_t)__cvta_generic_to_shared(&mbar[nxt]);
            asm volatile("mbarrier.arrive.expect_tx.shared.b64 _, [%0], %1;"
                         :: "r"(mn), "n"(EXP_TX) : "memory");
        }

        // gi prefetch (no h dependency; latency hidden under wait+matvec)
        float gir = 0.f, giz = 0.f, gin = 0.f, wt = 0.f;
        if (is_gate) {
            const size_t base = ((size_t)t * B_ + b) * G3_;
            gir = __ldg(&g_Gi[base + colg]);
            giz = __ldg(&g_Gi[base + 256 + colg]);
            gin = __ldg(&g_Gi[base + 512 + colg]);
            wt  = __ldg(&att[(size_t)b * T_ + t]);
        }

        // wait for h_t (both source CTAs' slices)
        if (t > 0) {
            uint32_t mc = (uint32_t)__cvta_generic_to_shared(&mbar[cur]);
            mbar_wait_cluster(mc, cur ? ph1 : ph0);
            if (cur) ph1 ^= 1; else ph0 ^= 1;
        }

        // ---- matvec: 128-k dot, broadcast h, 64 f32x2 FMAs, 4 acc chains ----
        unsigned long long a0 = 0ull, a1 = 0ull, a2 = 0ull, a3 = 0ull;
        {
            const double2* hp = (const double2*)&hb[cur][kq * 128];
#pragma unroll
            for (int i = 0; i < 32; i += 4) {
                double2 v0 = hp[i + 0];   // warp-uniform address -> broadcast
                double2 v1 = hp[i + 1];
                double2 v2 = hp[i + 2];
                double2 v3 = hp[i + 3];
                a0 = fma2(wq[2*i + 0], __double_as_longlong(v0.x), a0);
                a0 = fma2(wq[2*i + 1], __double_as_longlong(v0.y), a0);
                a1 = fma2(wq[2*i + 2], __double_as_longlong(v1.x), a1);
                a1 = fma2(wq[2*i + 3], __double_as_longlong(v1.y), a1);
                a2 = fma2(wq[2*i + 4], __double_as_longlong(v2.x), a2);
                a2 = fma2(wq[2*i + 5], __double_as_longlong(v2.y), a2);
                a3 = fma2(wq[2*i + 6], __double_as_longlong(v3.x), a3);
                a3 = fma2(wq[2*i + 7], __double_as_longlong(v3.y), a3);
            }
        }
        ghp[cur][kq][row] = unpack_sum(add2(add2(a0, a1), add2(a2, a3)));
        __syncthreads();

        // ---- gates (threads 0..127) + st.async to both CTAs ----
        if (is_gate) {
            const float sr_ = ghp[cur][0][tid]       + ghp[cur][1][tid];
            const float sz_ = ghp[cur][0][128 + tid] + ghp[cur][1][128 + tid];
            const float sn_ = ghp[cur][0][256 + tid] + ghp[cur][1][256 + tid];
            const float hprev = hreg;
            const float r = sigm(gir + sr_ + bhr);
            const float z = sigm(giz + sz_ + bhz);
            const float n = tanh_fast(gin + r * (sn_ + bhn));
            const float hnew = (1.f - z) * n + z * hprev;
            const float hg   = wt * hnew + (1.f - wt) * hprev;
            const float hv   = (t < Tmax) ? hg : hprev;   // always true; keeps form
            hreg = hv;

            // pack col pairs: even tid stores (hv[col], hv[col+1]) as b64
            const float hvo = __shfl_xor_sync(0xffffffffu, hv, 1);
            if ((tid & 1) == 0) {
                const unsigned long long pk = packf2(hv, hvo);
                uint32_t lh = (uint32_t)__cvta_generic_to_shared(
                    (const void*)&hb[nxt][colg]);
                uint32_t lm = (uint32_t)__cvta_generic_to_shared(&mbar[nxt]);
#pragma unroll
                for (int rdst = 0; rdst < 2; rdst++) {
                    uint32_t rh, rm;
                    asm volatile("mapa.shared::cluster.u32 %0, %1, %2;"
                                 : "=r"(rh) : "r"(lh), "r"(rdst));
                    asm volatile("mapa.shared::cluster.u32 %0, %1, %2;"
                                 : "=r"(rm) : "r"(lm), "r"(rdst));
                    asm volatile(
                        "st.async.shared::cluster.mbarrier::complete_tx::bytes.b64 "
                        "[%0], %1, [%2];"
                        :: "r"(rh), "l"(pk), "r"(rm) : "memory");
                }
            }
        }
    }

    // consume the final phase (ensures last st.async delivered before exit)
    {
        uint32_t mf = (uint32_t)__cvta_generic_to_shared(&mbar[Tmax & 1]);
        mbar_wait_cluster(mf, (Tmax & 1) ? ph1 : ph0);
    }
    if (is_gate) out[(size_t)b * H_ + colg] = hreg;

    asm volatile("barrier.cluster.arrive.aligned;" ::: "memory");
    asm volatile("barrier.cluster.wait.aligned;" ::: "memory");
}

// ======================= launch =======================
extern "C" void kernel_launch(void* const* d_in, const int* in_sizes, int n_in,
                              void* d_out, int out_size)
{
    const float* x       = (const float*)d_in[0];
    const float* att     = (const float*)d_in[1];
    const int*   lengths = (const int*)  d_in[2];
    const float* W_ih    = (const float*)d_in[3];
    const float* W_hh    = (const float*)d_in[4];
    const float* b_ih    = (const float*)d_in[5];
    const float* b_hh    = (const float*)d_in[6];
    float* out = (float*)d_out;
    (void)in_sizes; (void)n_in; (void)out_size;

    dim3 ggrid((B_ * T_) / BM, G3_ / BN);
    gi_gemm<<<ggrid, 256>>>(x, W_ih, b_ih, lengths);
    gru_rec<<<128, REC_THREADS>>>(att, lengths, W_hh, b_hh, out);
}

// round 9
// speedup vs baseline: 2.3452x; 2.3452x over previous
#include <cuda_runtime.h>
#include <cuda_bf16.h>
#include <mma.h>
#include <cstdint>

using namespace nvcuda;

#define B_  64
#define T_  2048
#define I_  256
#define H_  256
#define G3_ 768

// 402 MB scratch for precomputed input gates (NO bias): layout [t][b][768]
__device__ float g_Gi[(size_t)B_ * T_ * G3_];

// ======================= Phase 1: Gi = x @ W_ih^T  (wmma bf16 hi/lo) ==========
// CTA = 128(t) x 64(n) tile of one batch. 256 threads = 8 warps (4m x 2n),
// warp tile 32x32 = 2x2 m16n16k16 fragments. K slabs of 32.
// Split precision: v = hi + lo (both bf16); Gi = xh*Wh + xh*Wl + xl*Wh
// (error ~2^-18). fp32 accumulate; store direct to g_Gi (bias added in rec).

#define GBK 32
#define GLD 48   // padded ld (elements): 96 B rows, 16/32 B aligned frag ptrs

__global__ __launch_bounds__(256) void gi_gemm_wmma(
    const float* __restrict__ x, const float* __restrict__ W_ih,
    const int* __restrict__ lengths)
{
    const int mt    = blockIdx.x;          // 0..1023
    const int batch = mt >> 4;
    const int t0    = (mt & 15) * 128;
    if (t0 >= __ldg(&lengths[batch])) return;
    const int n0 = blockIdx.y * 64;

    __shared__ __nv_bfloat16 Ah[128][GLD], Al[128][GLD];
    __shared__ __nv_bfloat16 Bh[64][GLD],  Bl[64][GLD];

    const int tid  = threadIdx.x;
    const int warp = tid >> 5;
    const int wm   = warp >> 1;            // 0..3
    const int wn   = warp & 1;             // 0..1

    wmma::fragment<wmma::accumulator, 16, 16, 16, float> acc[2][2];
#pragma unroll
    for (int mi = 0; mi < 2; mi++)
#pragma unroll
        for (int ni = 0; ni < 2; ni++) wmma::fill_fragment(acc[mi][ni], 0.f);

    for (int ks = 0; ks < I_; ks += GBK) {
        // A tile: 128 x 32 fp32 -> hi/lo bf16. 1024 float4, 4 per thread.
#pragma unroll
        for (int j = 0; j < 4; j++) {
            const int idx = tid + j * 256;
            const int row = idx >> 3, c = (idx & 7) * 4;
            float4 v = *(const float4*)&x[(size_t)(batch * T_ + t0 + row) * I_ + ks + c];
            __nv_bfloat16 hx = __float2bfloat16(v.x);
            __nv_bfloat16 hy = __float2bfloat16(v.y);
            __nv_bfloat16 hz = __float2bfloat16(v.z);
            __nv_bfloat16 hw = __float2bfloat16(v.w);
            *(__nv_bfloat162*)&Ah[row][c]     = __nv_bfloat162(hx, hy);
            *(__nv_bfloat162*)&Ah[row][c + 2] = __nv_bfloat162(hz, hw);
            *(__nv_bfloat162*)&Al[row][c] = __nv_bfloat162(
                __float2bfloat16(v.x - __bfloat162float(hx)),
                __float2bfloat16(v.y - __bfloat162float(hy)));
            *(__nv_bfloat162*)&Al[row][c + 2] = __nv_bfloat162(
                __float2bfloat16(v.z - __bfloat162float(hz)),
                __float2bfloat16(v.w - __bfloat162float(hw)));
        }
        // B tile: 64 x 32 fp32 (W_ih rows n0..n0+63) -> hi/lo. 512 float4, 2/thread.
#pragma unroll
        for (int j = 0; j < 2; j++) {
            const int idx = tid + j * 256;
            const int row = idx >> 3, c = (idx & 7) * 4;
            float4 v = *(const float4*)&W_ih[(size_t)(n0 + row) * I_ + ks + c];
            __nv_bfloat16 hx = __float2bfloat16(v.x);
            __nv_bfloat16 hy = __float2bfloat16(v.y);
            __nv_bfloat16 hz = __float2bfloat16(v.z);
            __nv_bfloat16 hw = __float2bfloat16(v.w);
            *(__nv_bfloat162*)&Bh[row][c]     = __nv_bfloat162(hx, hy);
            *(__nv_bfloat162*)&Bh[row][c + 2] = __nv_bfloat162(hz, hw);
            *(__nv_bfloat162*)&Bl[row][c] = __nv_bfloat162(
                __float2bfloat16(v.x - __bfloat162float(hx)),
                __float2bfloat16(v.y - __bfloat162float(hy)));
            *(__nv_bfloat162*)&Bl[row][c + 2] = __nv_bfloat162(
                __float2bfloat16(v.z - __bfloat162float(hz)),
                __float2bfloat16(v.w - __bfloat162float(hw)));
        }
        __syncthreads();

#pragma unroll
        for (int kk = 0; kk < GBK; kk += 16) {
            wmma::fragment<wmma::matrix_a, 16, 16, 16, __nv_bfloat16,
                           wmma::row_major> ah[2], al[2];
            wmma::fragment<wmma::matrix_b, 16, 16, 16, __nv_bfloat16,
                           wmma::col_major> bh[2], bl[2];
#pragma unroll
            for (int mi = 0; mi < 2; mi++) {
                wmma::load_matrix_sync(ah[mi], &Ah[wm * 32 + mi * 16][kk], GLD);
                wmma::load_matrix_sync(al[mi], &Al[wm * 32 + mi * 16][kk], GLD);
            }
#pragma unroll
            for (int ni = 0; ni < 2; ni++) {
                wmma::load_matrix_sync(bh[ni], &Bh[wn * 32 + ni * 16][kk], GLD);
                wmma::load_matrix_sync(bl[ni], &Bl[wn * 32 + ni * 16][kk], GLD);
            }
#pragma unroll
            for (int mi = 0; mi < 2; mi++)
#pragma unroll
                for (int ni = 0; ni < 2; ni++) {
                    wmma::mma_sync(acc[mi][ni], ah[mi], bh[ni], acc[mi][ni]);
                    wmma::mma_sync(acc[mi][ni], ah[mi], bl[ni], acc[mi][ni]);
                    wmma::mma_sync(acc[mi][ni], al[mi], bh[ni], acc[mi][ni]);
                }
        }
        __syncthreads();
    }

    // store: m-row (t0+wm*32+mi*16) of batch -> stride between m-rows = B_*G3_
#pragma unroll
    for (int mi = 0; mi < 2; mi++)
#pragma unroll
        for (int ni = 0; ni < 2; ni++) {
            float* dst = &g_Gi[((size_t)(t0 + wm * 32 + mi * 16) * B_ + batch) * G3_
                               + n0 + wn * 32 + ni * 16];
            wmma::store_matrix_sync(dst, acc[mi][ni], (unsigned)(B_ * G3_),
                                    wmma::mem_row_major);
        }
}

// ======================= Phase 2: recurrence (R4 protocol) ====================
// 16 clusters of 8 CTAs, batches {4c..4c+3}. CTA rank r owns H-cols
// [r*32, r*32+32) for 3 gates (96 W rows); W in regs (16 f32x2/thread),
// h reads warp-uniform broadcasts. Exchange: st.async.b64 packed pairs to
// all 8 CTAs + one per-buffer mbar (tx=4096 B). No in-loop cluster barrier.
// Changes vs R4: tanh_fast (validated R7), b_ih added at gate (Gi has no bias).

#define REC_THREADS 768
#define EXP_TX 4096

__device__ __forceinline__ float sigm(float v) { return 1.f / (1.f + __expf(-v)); }
__device__ __forceinline__ float tanh_fast(float u) {
    const float t = __expf(-2.f * fabsf(u));
    const float m = (1.f - t) / (1.f + t);
    return copysignf(m, u);
}
__device__ __forceinline__ unsigned long long fma2(unsigned long long a,
                                                   unsigned long long b,
                                                   unsigned long long c) {
    unsigned long long d;
    asm("fma.rn.f32x2 %0, %1, %2, %3;" : "=l"(d) : "l"(a), "l"(b), "l"(c));
    return d;
}
__device__ __forceinline__ unsigned long long packf2(float lo, float hi) {
    unsigned long long d;
    asm("mov.b64 %0, {%1, %2};" : "=l"(d) : "f"(lo), "f"(hi));
    return d;
}
__device__ __forceinline__ float unpack_sum(unsigned long long v) {
    float lo, hi;
    asm("mov.b64 {%0, %1}, %2;" : "=f"(lo), "=f"(hi) : "l"(v));
    return lo + hi;
}
__device__ __forceinline__ void mbar_wait_cluster(uint32_t mbar, uint32_t parity) {
    uint32_t done;
    asm volatile(
        "{\n\t.reg .pred p;\n\t"
        "mbarrier.try_wait.parity.acquire.cluster.shared::cta.b64 p, [%1], %2;\n\t"
        "selp.b32 %0, 1, 0, p;\n\t}"
        : "=r"(done) : "r"(mbar), "r"(parity) : "memory");
    while (!done) {
        asm volatile(
            "{\n\t.reg .pred p;\n\t"
            "mbarrier.try_wait.parity.acquire.cluster.shared::cta.b64 p, [%1], %2, 0x989680;\n\t"
            "selp.b32 %0, 1, 0, p;\n\t}"
            : "=r"(done) : "r"(mbar), "r"(parity) : "memory");
    }
}

__global__ void __cluster_dims__(8, 1, 1) __launch_bounds__(REC_THREADS, 1)
gru_rec(const float* __restrict__ att, const int* __restrict__ lengths,
        const float* __restrict__ W_hh, const float* __restrict__ b_hh,
        const float* __restrict__ b_ih, float* __restrict__ out)
{
    __shared__ alignas(16) float hb[2][4][256];   // [buf][batch][col]
    __shared__ float ghp[3][8][4][32];            // [gate][kc][batch][lane]
    __shared__ alignas(8) unsigned long long mbar[2];

    uint32_t rank;
    asm("mov.u32 %0, %%cluster_ctarank;" : "=r"(rank));
    const int cid = blockIdx.x >> 3;
    const int b0  = cid * 4;

    const int tid  = threadIdx.x;
    const int warp = tid >> 5;
    const int lane = tid & 31;
    const int rg   = warp >> 3;        // gate 0..2
    const int kc   = warp & 7;         // k chunk / source rank

    const int grow = rg * 256 + (int)rank * 32 + lane;
    unsigned long long wq[16];
#pragma unroll
    for (int i = 0; i < 8; i++) {
        float4 v = *(const float4*)&W_hh[(size_t)grow * H_ + kc * 32 + i * 4];
        wq[2 * i + 0] = packf2(v.x, v.y);
        wq[2 * i + 1] = packf2(v.z, v.w);
    }

    for (int i = tid; i < 4 * 256; i += REC_THREADS) ((float*)hb[0])[i] = 0.f;
    if (tid < 2) {
        uint32_t m = (uint32_t)__cvta_generic_to_shared(&mbar[tid]);
        asm volatile("mbarrier.init.shared.b64 [%0], 1;" :: "r"(m) : "memory");
    }

    const int gb   = tid >> 5;
    const int gj   = tid & 31;
    const int col  = (int)rank * 32 + gj;
    const int myb  = b0 + gb;
    float bhr = 0.f, bhz = 0.f, bhn = 0.f;
    float bir = 0.f, biz = 0.f, bin = 0.f;
    int mylen = 0;
    if (tid < 128) {
        bhr = b_hh[col];        bir = b_ih[col];
        bhz = b_hh[256 + col];  biz = b_ih[256 + col];
        bhn = b_hh[512 + col];  bin = b_ih[512 + col];
        mylen = lengths[myb];
    }
    const int Tmax = max(max(__ldg(&lengths[b0]),     __ldg(&lengths[b0 + 1])),
                         max(__ldg(&lengths[b0 + 2]), __ldg(&lengths[b0 + 3])));

    __syncthreads();
    asm volatile("barrier.cluster.arrive.aligned;" ::: "memory");
    asm volatile("barrier.cluster.wait.aligned;" ::: "memory");

    uint32_t ph0 = 0, ph1 = 0;

    for (int t = 0; t < Tmax; t++) {
        const int cur = t & 1, nxt = cur ^ 1;

        if (tid == 0) {
            uint32_t mn = (uint32_t)__cvta_generic_to_shared(&mbar[nxt]);
            asm volatile("mbarrier.arrive.expect_tx.shared.b64 _, [%0], %1;"
                         :: "r"(mn), "n"(EXP_TX) : "memory");
        }

        float gir = 0.f, giz = 0.f, gin = 0.f, wt = 0.f;
        if (tid < 128) {
            const size_t base = ((size_t)t * B_ + myb) * G3_;
            gir = __ldg(&g_Gi[base + col]) + bir;
            giz = __ldg(&g_Gi[base + 256 + col]) + biz;
            gin = __ldg(&g_Gi[base + 512 + col]) + bin;
            wt  = __ldg(&att[(size_t)myb * T_ + t]);
        }

        if (t > 0) {
            uint32_t mc = (uint32_t)__cvta_generic_to_shared(&mbar[cur]);
            mbar_wait_cluster(mc, cur ? ph1 : ph0);
            if (cur) ph1 ^= 1; else ph0 ^= 1;
        }

        unsigned long long a0 = 0ull, a1 = 0ull, a2 = 0ull, a3 = 0ull;
        {
            const double2* h0 = (const double2*)&hb[cur][0][kc * 32];
            const double2* h1 = (const double2*)&hb[cur][1][kc * 32];
            const double2* h2 = (const double2*)&hb[cur][2][kc * 32];
            const double2* h3 = (const double2*)&hb[cur][3][kc * 32];
#pragma unroll
            for (int i = 0; i < 8; i++) {
                double2 v0 = h0[i];   // warp-uniform address -> broadcast
                double2 v1 = h1[i];
                double2 v2 = h2[i];
                double2 v3 = h3[i];
                a0 = fma2(wq[2*i],   __double_as_longlong(v0.x), a0);
                a1 = fma2(wq[2*i],   __double_as_longlong(v1.x), a1);
                a2 = fma2(wq[2*i],   __double_as_longlong(v2.x), a2);
                a3 = fma2(wq[2*i],   __double_as_longlong(v3.x), a3);
                a0 = fma2(wq[2*i+1], __double_as_longlong(v0.y), a0);
                a1 = fma2(wq[2*i+1], __double_as_longlong(v1.y), a1);
                a2 = fma2(wq[2*i+1], __double_as_longlong(v2.y), a2);
                a3 = fma2(wq[2*i+1], __double_as_longlong(v3.y), a3);
            }
        }
        ghp[rg][kc][0][lane] = unpack_sum(a0);
        ghp[rg][kc][1][lane] = unpack_sum(a1);
        ghp[rg][kc][2][lane] = unpack_sum(a2);
        ghp[rg][kc][3][lane] = unpack_sum(a3);
        __syncthreads();

        if (tid < 128) {
            float sr_ = 0.f, sz_ = 0.f, sn_ = 0.f;
#pragma unroll
            for (int k = 0; k < 8; k++) {
                sr_ += ghp[0][k][gb][gj];
                sz_ += ghp[1][k][gb][gj];
                sn_ += ghp[2][k][gb][gj];
            }
            const float hprev = hb[cur][gb][col];
            const float r = sigm(gir + sr_ + bhr);
            const float z = sigm(giz + sz_ + bhz);
            const float n = tanh_fast(gin + r * (sn_ + bhn));
            const float hnew = (1.f - z) * n + z * hprev;
            const float hg   = wt * hnew + (1.f - wt) * hprev;
            const float hv   = (t < mylen) ? hg : hprev;

            const float hvo = __shfl_xor_sync(0xffffffffu, hv, 1);
            if ((gj & 1) == 0) {
                const unsigned long long pk = packf2(hv, hvo);
                uint32_t lh = (uint32_t)__cvta_generic_to_shared(
                    (const void*)&hb[nxt][gb][col]);
                uint32_t lm = (uint32_t)__cvta_generic_to_shared(&mbar[nxt]);
#pragma unroll
                for (int rdst = 0; rdst < 8; rdst++) {
                    uint32_t rh, rm;
                    asm volatile("mapa.shared::cluster.u32 %0, %1, %2;"
                                 : "=r"(rh) : "r"(lh), "r"(rdst));
                    asm volatile("mapa.shared::cluster.u32 %0, %1, %2;"
                                 : "=r"(rm) : "r"(lm), "r"(rdst));
                    asm volatile(
                        "st.async.shared::cluster.mbarrier::complete_tx::bytes.b64 "
                        "[%0], %1, [%2];"
                        :: "r"(rh), "l"(pk), "r"(rm) : "memory");
                }
            }
        }
    }

    {
        uint32_t mf = (uint32_t)__cvta_generic_to_shared(&mbar[Tmax & 1]);
        mbar_wait_cluster(mf, (Tmax & 1) ? ph1 : ph0);
    }
    if (tid < 128) out[(size_t)myb * H_ + col] = hb[Tmax & 1][gb][col];

    asm volatile("barrier.cluster.arrive.aligned;" ::: "memory");
    asm volatile("barrier.cluster.wait.aligned;" ::: "memory");
}

// ======================= launch =======================
extern "C" void kernel_launch(void* const* d_in, const int* in_sizes, int n_in,
                              void* d_out, int out_size)
{
    const float* x       = (const float*)d_in[0];
    const float* att     = (const float*)d_in[1];
    const int*   lengths = (const int*)  d_in[2];
    const float* W_ih    = (const float*)d_in[3];
    const float* W_hh    = (const float*)d_in[4];
    const float* b_ih    = (const float*)d_in[5];
    const float* b_hh    = (const float*)d_in[6];
    float* out = (float*)d_out;
    (void)in_sizes; (void)n_in; (void)out_size;

    dim3 ggrid(1024, 12);   // 1024 m-tiles x 12 n-tiles (768/64)
    gi_gemm_wmma<<<ggrid, 256>>>(x, W_ih, lengths);
    gru_rec<<<128, REC_THREADS>>>(att, lengths, W_hh, b_hh, b_ih, out);
}

// round 10
// speedup vs baseline: 2.6658x; 1.1367x over previous
#include <cuda_runtime.h>
#include <cuda_bf16.h>
#include <mma.h>
#include <cstdint>

using namespace nvcuda;

#define B_  64
#define T_  2048
#define I_  256
#define H_  256
#define G3_ 768

// 402 MB scratch for precomputed input gates (NO bias): layout [t][b][768]
__device__ float g_Gi[(size_t)B_ * T_ * G3_];

// ======================= Phase 1: Gi = x @ W_ih^T  (wmma bf16 hi/lo) ==========
// (unchanged from R9 — measured ~460 us, rel_err contribution ~4e-6)

#define GBK 32
#define GLD 48

__global__ __launch_bounds__(256) void gi_gemm_wmma(
    const float* __restrict__ x, const float* __restrict__ W_ih,
    const int* __restrict__ lengths)
{
    const int mt    = blockIdx.x;
    const int batch = mt >> 4;
    const int t0    = (mt & 15) * 128;
    if (t0 >= __ldg(&lengths[batch])) return;
    const int n0 = blockIdx.y * 64;

    __shared__ __nv_bfloat16 Ah[128][GLD], Al[128][GLD];
    __shared__ __nv_bfloat16 Bh[64][GLD],  Bl[64][GLD];

    const int tid  = threadIdx.x;
    const int warp = tid >> 5;
    const int wm   = warp >> 1;
    const int wn   = warp & 1;

    wmma::fragment<wmma::accumulator, 16, 16, 16, float> acc[2][2];
#pragma unroll
    for (int mi = 0; mi < 2; mi++)
#pragma unroll
        for (int ni = 0; ni < 2; ni++) wmma::fill_fragment(acc[mi][ni], 0.f);

    for (int ks = 0; ks < I_; ks += GBK) {
#pragma unroll
        for (int j = 0; j < 4; j++) {
            const int idx = tid + j * 256;
            const int row = idx >> 3, c = (idx & 7) * 4;
            float4 v = *(const float4*)&x[(size_t)(batch * T_ + t0 + row) * I_ + ks + c];
            __nv_bfloat16 hx = __float2bfloat16(v.x);
            __nv_bfloat16 hy = __float2bfloat16(v.y);
            __nv_bfloat16 hz = __float2bfloat16(v.z);
            __nv_bfloat16 hw = __float2bfloat16(v.w);
            *(__nv_bfloat162*)&Ah[row][c]     = __nv_bfloat162(hx, hy);
            *(__nv_bfloat162*)&Ah[row][c + 2] = __nv_bfloat162(hz, hw);
            *(__nv_bfloat162*)&Al[row][c] = __nv_bfloat162(
                __float2bfloat16(v.x - __bfloat162float(hx)),
                __float2bfloat16(v.y - __bfloat162float(hy)));
            *(__nv_bfloat162*)&Al[row][c + 2] = __nv_bfloat162(
                __float2bfloat16(v.z - __bfloat162float(hz)),
                __float2bfloat16(v.w - __bfloat162float(hw)));
        }
#pragma unroll
        for (int j = 0; j < 2; j++) {
            const int idx = tid + j * 256;
            const int row = idx >> 3, c = (idx & 7) * 4;
            float4 v = *(const float4*)&W_ih[(size_t)(n0 + row) * I_ + ks + c];
            __nv_bfloat16 hx = __float2bfloat16(v.x);
            __nv_bfloat16 hy = __float2bfloat16(v.y);
            __nv_bfloat16 hz = __float2bfloat16(v.z);
            __nv_bfloat16 hw = __float2bfloat16(v.w);
            *(__nv_bfloat162*)&Bh[row][c]     = __nv_bfloat162(hx, hy);
            *(__nv_bfloat162*)&Bh[row][c + 2] = __nv_bfloat162(hz, hw);
            *(__nv_bfloat162*)&Bl[row][c] = __nv_bfloat162(
                __float2bfloat16(v.x - __bfloat162float(hx)),
                __float2bfloat16(v.y - __bfloat162float(hy)));
            *(__nv_bfloat162*)&Bl[row][c + 2] = __nv_bfloat162(
                __float2bfloat16(v.z - __bfloat162float(hz)),
                __float2bfloat16(v.w - __bfloat162float(hw)));
        }
        __syncthreads();

#pragma unroll
        for (int kk = 0; kk < GBK; kk += 16) {
            wmma::fragment<wmma::matrix_a, 16, 16, 16, __nv_bfloat16,
                           wmma::row_major> ah[2], al[2];
            wmma::fragment<wmma::matrix_b, 16, 16, 16, __nv_bfloat16,
                           wmma::col_major> bh[2], bl[2];
#pragma unroll
            for (int mi = 0; mi < 2; mi++) {
                wmma::load_matrix_sync(ah[mi], &Ah[wm * 32 + mi * 16][kk], GLD);
                wmma::load_matrix_sync(al[mi], &Al[wm * 32 + mi * 16][kk], GLD);
            }
#pragma unroll
            for (int ni = 0; ni < 2; ni++) {
                wmma::load_matrix_sync(bh[ni], &Bh[wn * 32 + ni * 16][kk], GLD);
                wmma::load_matrix_sync(bl[ni], &Bl[wn * 32 + ni * 16][kk], GLD);
            }
#pragma unroll
            for (int mi = 0; mi < 2; mi++)
#pragma unroll
                for (int ni = 0; ni < 2; ni++) {
                    wmma::mma_sync(acc[mi][ni], ah[mi], bh[ni], acc[mi][ni]);
                    wmma::mma_sync(acc[mi][ni], ah[mi], bl[ni], acc[mi][ni]);
                    wmma::mma_sync(acc[mi][ni], al[mi], bh[ni], acc[mi][ni]);
                }
        }
        __syncthreads();
    }

#pragma unroll
    for (int mi = 0; mi < 2; mi++)
#pragma unroll
        for (int ni = 0; ni < 2; ni++) {
            float* dst = &g_Gi[((size_t)(t0 + wm * 32 + mi * 16) * B_ + batch) * G3_
                               + n0 + wn * 32 + ni * 16];
            wmma::store_matrix_sync(dst, acc[mi][ni], (unsigned)(B_ * G3_),
                                    wmma::mem_row_major);
        }
}

// ======================= Phase 2: recurrence (HMMA matvec) ====================
// 16 clusters of 8 CTAs, batches {4c..4c+3}. CTA rank r owns H-cols
// [r*32,+32) x 3 gates = 96 local rows. Warp = (m-tile 0..5, kc 0..3):
// rows m*16..+16, k slice kc*64..+64 (4 k-steps of 16).
// A = W_hh split hi/lo bf16, LOOP-INVARIANT in 32 regs (8 frag-regs x 4 ks).
// B's 8 N-columns = 4 batches x {h_hi, h_lo}: 2 MMA passes (A=Whi, A=Wlo)
// give all 4 cross terms; gh(row,b) = c[2b] + c[2b+1].
// h exchange carries {hh2, hl2} bf16x2 pairs via st.async.b64 into
// hx[buf][batch][pair][2] (264-word batch stride -> conflict-free B LDS).
// Gate threads keep exact fp32 h in a register. Protocol = R4 lineage.

#define REC_THREADS 768
#define EXP_TX 4096
#define HXW 1056                         // 4 batches * 264 words

__device__ __forceinline__ float sigm(float v) { return 1.f / (1.f + __expf(-v)); }
__device__ __forceinline__ float tanh_fast(float u) {
    const float t = __expf(-2.f * fabsf(u));
    const float m = (1.f - t) / (1.f + t);
    return copysignf(m, u);
}
__device__ __forceinline__ uint32_t split_pack(float2 v, uint32_t& lo_pack) {
    uint16_t h0, h1, l0, l1;
    asm("cvt.rn.bf16.f32 %0, %1;" : "=h"(h0) : "f"(v.x));
    asm("cvt.rn.bf16.f32 %0, %1;" : "=h"(h1) : "f"(v.y));
    float r0 = v.x - __uint_as_float((uint32_t)h0 << 16);
    float r1 = v.y - __uint_as_float((uint32_t)h1 << 16);
    asm("cvt.rn.bf16.f32 %0, %1;" : "=h"(l0) : "f"(r0));
    asm("cvt.rn.bf16.f32 %0, %1;" : "=h"(l1) : "f"(r1));
    lo_pack = (uint32_t)l0 | ((uint32_t)l1 << 16);
    return (uint32_t)h0 | ((uint32_t)h1 << 16);
}
__device__ __forceinline__ void mma_bf16(
    float& c0, float& c1, float& c2, float& c3,
    uint32_t a0, uint32_t a1, uint32_t a2, uint32_t a3,
    uint32_t b0, uint32_t b1)
{
    asm("mma.sync.aligned.m16n8k16.row.col.f32.bf16.bf16.f32 "
        "{%0,%1,%2,%3}, {%4,%5,%6,%7}, {%8,%9}, {%0,%1,%2,%3};"
        : "+f"(c0), "+f"(c1), "+f"(c2), "+f"(c3)
        : "r"(a0), "r"(a1), "r"(a2), "r"(a3), "r"(b0), "r"(b1));
}
__device__ __forceinline__ uint32_t prmt(uint32_t a, uint32_t b, uint32_t s) {
    uint32_t d;
    asm("prmt.b32 %0, %1, %2, %3;" : "=r"(d) : "r"(a), "r"(b), "r"(s));
    return d;
}
__device__ __forceinline__ void mbar_wait_cluster(uint32_t mbar, uint32_t parity) {
    uint32_t done;
    asm volatile(
        "{\n\t.reg .pred p;\n\t"
        "mbarrier.try_wait.parity.acquire.cluster.shared::cta.b64 p, [%1], %2;\n\t"
        "selp.b32 %0, 1, 0, p;\n\t}"
        : "=r"(done) : "r"(mbar), "r"(parity) : "memory");
    while (!done) {
        asm volatile(
            "{\n\t.reg .pred p;\n\t"
            "mbarrier.try_wait.parity.acquire.cluster.shared::cta.b64 p, [%1], %2, 0x989680;\n\t"
            "selp.b32 %0, 1, 0, p;\n\t}"
            : "=r"(done) : "r"(mbar), "r"(parity) : "memory");
    }
}

__global__ void __cluster_dims__(8, 1, 1) __launch_bounds__(REC_THREADS, 1)
gru_rec(const float* __restrict__ att, const int* __restrict__ lengths,
        const float* __restrict__ W_hh, const float* __restrict__ b_hh,
        const float* __restrict__ b_ih, float* __restrict__ out)
{
    __shared__ uint32_t hx[2][HXW];       // [buf][b*264 + pair*2 + sel]
    __shared__ float ghp[4][4][104];      // [kc][batch][row 0..95, pad 104]
    __shared__ alignas(8) unsigned long long mbar[2];

    uint32_t rank;
    asm("mov.u32 %0, %%cluster_ctarank;" : "=r"(rank));
    const int cid = blockIdx.x >> 3;
    const int b0  = cid * 4;

    const int tid  = threadIdx.x;
    const int warp = tid >> 5;
    const int lane = tid & 31;
    const int m    = warp >> 2;           // m-tile 0..5
    const int kc   = warp & 3;            // k slice 0..3
    const int q    = lane & 3;
    const int rg2  = lane >> 2;           // 0..7

    // ---- loop-invariant A fragments (W_hh hi/lo) ----
    const int row0 = m * 16 + rg2;                               // local row
    const int grow = (row0 >> 5) * 256 + (int)rank * 32 + (row0 & 31);
    uint32_t ahi[4][4], alo[4][4];
#pragma unroll
    for (int ks = 0; ks < 4; ks++) {
        const int k0 = kc * 64 + ks * 16 + q * 2;
        float2 v00 = *(const float2*)&W_hh[(size_t)grow * H_ + k0];
        float2 v10 = *(const float2*)&W_hh[(size_t)(grow + 8) * H_ + k0];
        float2 v01 = *(const float2*)&W_hh[(size_t)grow * H_ + k0 + 8];
        float2 v11 = *(const float2*)&W_hh[(size_t)(grow + 8) * H_ + k0 + 8];
        ahi[ks][0] = split_pack(v00, alo[ks][0]);
        ahi[ks][1] = split_pack(v10, alo[ks][1]);
        ahi[ks][2] = split_pack(v01, alo[ks][2]);
        ahi[ks][3] = split_pack(v11, alo[ks][3]);
    }

    // ---- zero h buffer 0, init mbarriers ----
    for (int i = tid; i < HXW; i += REC_THREADS) hx[0][i] = 0u;
    if (tid < 2) {
        uint32_t mb = (uint32_t)__cvta_generic_to_shared(&mbar[tid]);
        asm volatile("mbarrier.init.shared.b64 [%0], 1;" :: "r"(mb) : "memory");
    }

    // ---- gate constants (threads 0..127: gb = tid>>5, gj = tid&31) ----
    const int gb   = tid >> 5;
    const int gj   = tid & 31;
    const int col  = (int)rank * 32 + gj;
    const int myb  = b0 + gb;
    float bcr = 0.f, bcz = 0.f, bcn = 0.f, bhn = 0.f;
    int mylen = 0;
    if (tid < 128) {
        bcr = b_ih[col] + b_hh[col];
        bcz = b_ih[256 + col] + b_hh[256 + col];
        bcn = b_ih[512 + col];
        bhn = b_hh[512 + col];
        mylen = lengths[myb];
    }
    float hreg = 0.f;
    const int Tmax = max(max(__ldg(&lengths[b0]),     __ldg(&lengths[b0 + 1])),
                         max(__ldg(&lengths[b0 + 2]), __ldg(&lengths[b0 + 3])));

    // ---- lane constants for B-fragment loads ----
    const int wb = (lane >> 3) * 264 + kc * 64 + q * 2 + ((lane >> 2) & 1);

    __syncthreads();
    asm volatile("barrier.cluster.arrive.aligned;" ::: "memory");
    asm volatile("barrier.cluster.wait.aligned;" ::: "memory");

    uint32_t ph0 = 0, ph1 = 0;

    for (int t = 0; t < Tmax; t++) {
        const int cur = t & 1, nxt = cur ^ 1;

        // arm next buffer (non-gate warp)
        if (tid == 256) {
            uint32_t mn = (uint32_t)__cvta_generic_to_shared(&mbar[nxt]);
            asm volatile("mbarrier.arrive.expect_tx.shared.b64 _, [%0], %1;"
                         :: "r"(mn), "n"(EXP_TX) : "memory");
        }

        // gi prefetch + bias fold (no h dependency)
        float gir = 0.f, giz = 0.f, gin = 0.f, wt = 0.f;
        if (tid < 128) {
            const size_t base = ((size_t)t * B_ + myb) * G3_;
            gir = __ldg(&g_Gi[base + col]) + bcr;
            giz = __ldg(&g_Gi[base + 256 + col]) + bcz;
            gin = __ldg(&g_Gi[base + 512 + col]) + bcn;
            wt  = __ldg(&att[(size_t)myb * T_ + t]);
        }

        if (t > 0) {
            uint32_t mc = (uint32_t)__cvta_generic_to_shared(&mbar[cur]);
            mbar_wait_cluster(mc, cur ? ph1 : ph0);
            if (cur) ph1 ^= 1; else ph0 ^= 1;
        }

        // ---- HMMA matvec: 2 passes (Whi, Wlo) over B = [4b x {hh,hl}] ----
        float c0 = 0.f, c1 = 0.f, c2 = 0.f, c3 = 0.f;
        {
            const uint32_t* hxc = hx[cur];
#pragma unroll
            for (int ks = 0; ks < 4; ks++) {
                const uint32_t bf0 = hxc[wb + ks * 16];
                const uint32_t bf1 = hxc[wb + ks * 16 + 8];
                mma_bf16(c0, c1, c2, c3,
                         ahi[ks][0], ahi[ks][1], ahi[ks][2], ahi[ks][3], bf0, bf1);
                mma_bf16(c0, c1, c2, c3,
                         alo[ks][0], alo[ks][1], alo[ks][2], alo[ks][3], bf0, bf1);
            }
        }
        // gh(row, b=q) = hi-col + lo-col
        ghp[kc][q][m * 16 + rg2]     = c0 + c1;
        ghp[kc][q][m * 16 + 8 + rg2] = c2 + c3;
        __syncthreads();

        // ---- gates (threads 0..127) + split/pack/send ----
        if (tid < 128) {
            float sr_ = 0.f, sz_ = 0.f, sn_ = 0.f;
#pragma unroll
            for (int k = 0; k < 4; k++) {
                sr_ += ghp[k][gb][gj];
                sz_ += ghp[k][gb][32 + gj];
                sn_ += ghp[k][gb][64 + gj];
            }
            const float hprev = hreg;
            const float r = sigm(gir + sr_);
            const float z = sigm(giz + sz_);
            const float n = tanh_fast(gin + r * (sn_ + bhn));
            const float hnew = (1.f - z) * n + z * hprev;
            const float hg   = wt * hnew + (1.f - wt) * hprev;
            const float hv   = (t < mylen) ? hg : hprev;
            hreg = hv;

            // split hv -> {hh, hl} bf16, pack with neighbor column
            uint16_t hh16, hl16;
            asm("cvt.rn.bf16.f32 %0, %1;" : "=h"(hh16) : "f"(hv));
            const float hlr = hv - __uint_as_float((uint32_t)hh16 << 16);
            asm("cvt.rn.bf16.f32 %0, %1;" : "=h"(hl16) : "f"(hlr));
            const uint32_t own = (uint32_t)hh16 | ((uint32_t)hl16 << 16);
            const uint32_t oth = __shfl_down_sync(0xffffffffu, own, 1);
            if ((gj & 1) == 0) {
                const uint32_t hh2 = prmt(own, oth, 0x5410u);  // {hh_e, hh_o}
                const uint32_t hl2 = prmt(own, oth, 0x7632u);  // {hl_e, hl_o}
                unsigned long long pk;
                asm("mov.b64 %0, {%1, %2};" : "=l"(pk) : "r"(hh2), "r"(hl2));
                const int pair = (int)rank * 16 + (gj >> 1);
                uint32_t lh = (uint32_t)__cvta_generic_to_shared(
                    &hx[nxt][gb * 264 + pair * 2]);
                uint32_t lm = (uint32_t)__cvta_generic_to_shared(&mbar[nxt]);
#pragma unroll
                for (int rdst = 0; rdst < 8; rdst++) {
                    uint32_t rh, rm;
                    asm volatile("mapa.shared::cluster.u32 %0, %1, %2;"
                                 : "=r"(rh) : "r"(lh), "r"(rdst));
                    asm volatile("mapa.shared::cluster.u32 %0, %1, %2;"
                                 : "=r"(rm) : "r"(lm), "r"(rdst));
                    asm volatile(
                        "st.async.shared::cluster.mbarrier::complete_tx::bytes.b64 "
                        "[%0], %1, [%2];"
                        :: "r"(rh), "l"(pk), "r"(rm) : "memory");
                }
            }
        }
    }

    // drain final phase before exit
    {
        uint32_t mf = (uint32_t)__cvta_generic_to_shared(&mbar[Tmax & 1]);
        mbar_wait_cluster(mf, (Tmax & 1) ? ph1 : ph0);
    }
    if (tid < 128) out[(size_t)myb * H_ + col] = hreg;

    asm volatile("barrier.cluster.arrive.aligned;" ::: "memory");
    asm volatile("barrier.cluster.wait.aligned;" ::: "memory");
}

// ======================= launch =======================
extern "C" void kernel_launch(void* const* d_in, const int* in_sizes, int n_in,
                              void* d_out, int out_size)
{
    const float* x       = (const float*)d_in[0];
    const float* att     = (const float*)d_in[1];
    const int*   lengths = (const int*)  d_in[2];
    const float* W_ih    = (const float*)d_in[3];
    const float* W_hh    = (const float*)d_in[4];
    const float* b_ih    = (const float*)d_in[5];
    const float* b_hh    = (const float*)d_in[6];
    float* out = (float*)d_out;
    (void)in_sizes; (void)n_in; (void)out_size;

    dim3 ggrid(1024, 12);
    gi_gemm_wmma<<<ggrid, 256>>>(x, W_ih, lengths);
    gru_rec<<<128, REC_THREADS>>>(att, lengths, W_hh, b_hh, b_ih, out);
}

// round 11
// speedup vs baseline: 2.7452x; 1.0298x over previous
#include <cuda_runtime.h>
#include <cuda_bf16.h>
#include <mma.h>
#include <cstdint>

using namespace nvcuda;

#define B_  64
#define T_  2048
#define I_  256
#define H_  256
#define G3_ 768

// 402 MB scratch for precomputed input gates (NO bias): layout [t][b][768]
__device__ float g_Gi[(size_t)B_ * T_ * G3_];

// ======================= Phase 1: Gi = x @ W_ih^T  (wmma bf16 hi/lo) ==========
// (unchanged from R9 — measured ~460 us, rel_err contribution ~4e-6)

#define GBK 32
#define GLD 48

__global__ __launch_bounds__(256) void gi_gemm_wmma(
    const float* __restrict__ x, const float* __restrict__ W_ih,
    const int* __restrict__ lengths)
{
    const int mt    = blockIdx.x;
    const int batch = mt >> 4;
    const int t0    = (mt & 15) * 128;
    if (t0 >= __ldg(&lengths[batch])) return;
    const int n0 = blockIdx.y * 64;

    __shared__ __nv_bfloat16 Ah[128][GLD], Al[128][GLD];
    __shared__ __nv_bfloat16 Bh[64][GLD],  Bl[64][GLD];

    const int tid  = threadIdx.x;
    const int warp = tid >> 5;
    const int wm   = warp >> 1;
    const int wn   = warp & 1;

    wmma::fragment<wmma::accumulator, 16, 16, 16, float> acc[2][2];
#pragma unroll
    for (int mi = 0; mi < 2; mi++)
#pragma unroll
        for (int ni = 0; ni < 2; ni++) wmma::fill_fragment(acc[mi][ni], 0.f);

    for (int ks = 0; ks < I_; ks += GBK) {
#pragma unroll
        for (int j = 0; j < 4; j++) {
            const int idx = tid + j * 256;
            const int row = idx >> 3, c = (idx & 7) * 4;
            float4 v = *(const float4*)&x[(size_t)(batch * T_ + t0 + row) * I_ + ks + c];
            __nv_bfloat16 hx = __float2bfloat16(v.x);
            __nv_bfloat16 hy = __float2bfloat16(v.y);
            __nv_bfloat16 hz = __float2bfloat16(v.z);
            __nv_bfloat16 hw = __float2bfloat16(v.w);
            *(__nv_bfloat162*)&Ah[row][c]     = __nv_bfloat162(hx, hy);
            *(__nv_bfloat162*)&Ah[row][c + 2] = __nv_bfloat162(hz, hw);
            *(__nv_bfloat162*)&Al[row][c] = __nv_bfloat162(
                __float2bfloat16(v.x - __bfloat162float(hx)),
                __float2bfloat16(v.y - __bfloat162float(hy)));
            *(__nv_bfloat162*)&Al[row][c + 2] = __nv_bfloat162(
                __float2bfloat16(v.z - __bfloat162float(hz)),
                __float2bfloat16(v.w - __bfloat162float(hw)));
        }
#pragma unroll
        for (int j = 0; j < 2; j++) {
            const int idx = tid + j * 256;
            const int row = idx >> 3, c = (idx & 7) * 4;
            float4 v = *(const float4*)&W_ih[(size_t)(n0 + row) * I_ + ks + c];
            __nv_bfloat16 hx = __float2bfloat16(v.x);
            __nv_bfloat16 hy = __float2bfloat16(v.y);
            __nv_bfloat16 hz = __float2bfloat16(v.z);
            __nv_bfloat16 hw = __float2bfloat16(v.w);
            *(__nv_bfloat162*)&Bh[row][c]     = __nv_bfloat162(hx, hy);
            *(__nv_bfloat162*)&Bh[row][c + 2] = __nv_bfloat162(hz, hw);
            *(__nv_bfloat162*)&Bl[row][c] = __nv_bfloat162(
                __float2bfloat16(v.x - __bfloat162float(hx)),
                __float2bfloat16(v.y - __bfloat162float(hy)));
            *(__nv_bfloat162*)&Bl[row][c + 2] = __nv_bfloat162(
                __float2bfloat16(v.z - __bfloat162float(hz)),
                __float2bfloat16(v.w - __bfloat162float(hw)));
        }
        __syncthreads();

#pragma unroll
        for (int kk = 0; kk < GBK; kk += 16) {
            wmma::fragment<wmma::matrix_a, 16, 16, 16, __nv_bfloat16,
                           wmma::row_major> ah[2], al[2];
            wmma::fragment<wmma::matrix_b, 16, 16, 16, __nv_bfloat16,
                           wmma::col_major> bh[2], bl[2];
#pragma unroll
            for (int mi = 0; mi < 2; mi++) {
                wmma::load_matrix_sync(ah[mi], &Ah[wm * 32 + mi * 16][kk], GLD);
                wmma::load_matrix_sync(al[mi], &Al[wm * 32 + mi * 16][kk], GLD);
            }
#pragma unroll
            for (int ni = 0; ni < 2; ni++) {
                wmma::load_matrix_sync(bh[ni], &Bh[wn * 32 + ni * 16][kk], GLD);
                wmma::load_matrix_sync(bl[ni], &Bl[wn * 32 + ni * 16][kk], GLD);
            }
#pragma unroll
            for (int mi = 0; mi < 2; mi++)
#pragma unroll
                for (int ni = 0; ni < 2; ni++) {
                    wmma::mma_sync(acc[mi][ni], ah[mi], bh[ni], acc[mi][ni]);
                    wmma::mma_sync(acc[mi][ni], ah[mi], bl[ni], acc[mi][ni]);
                    wmma::mma_sync(acc[mi][ni], al[mi], bh[ni], acc[mi][ni]);
                }
        }
        __syncthreads();
    }

#pragma unroll
    for (int mi = 0; mi < 2; mi++)
#pragma unroll
        for (int ni = 0; ni < 2; ni++) {
            float* dst = &g_Gi[((size_t)(t0 + wm * 32 + mi * 16) * B_ + batch) * G3_
                               + n0 + wn * 32 + ni * 16];
            wmma::store_matrix_sync(dst, acc[mi][ni], (unsigned)(B_ * G3_),
                                    wmma::mem_row_major);
        }
}

// ======================= Phase 2: recurrence (HMMA matvec) ====================
// R10 structure. R11 changes:
//  (a) wait scope dropped cluster -> CTA: st.async data lands in OUR smem and
//      is ordered by the tx-completion of OUR mbarrier (same pattern as
//      multicast-TMA waited with acquire.cta). Avoids per-step per-warp
//      CCTL.IVALL (L1 flush) that cluster-scope acquire forces.
//  (b) mapa hoisted out of the loop: peer addresses are precomputed once;
//      buffer/mbar variants derived by constant deltas.

#define REC_THREADS 768
#define EXP_TX 4096
#define HXW 1056                         // 4 batches * 264 words

__device__ __forceinline__ float sigm(float v) { return 1.f / (1.f + __expf(-v)); }
__device__ __forceinline__ float tanh_fast(float u) {
    const float t = __expf(-2.f * fabsf(u));
    const float m = (1.f - t) / (1.f + t);
    return copysignf(m, u);
}
__device__ __forceinline__ uint32_t split_pack(float2 v, uint32_t& lo_pack) {
    uint16_t h0, h1, l0, l1;
    asm("cvt.rn.bf16.f32 %0, %1;" : "=h"(h0) : "f"(v.x));
    asm("cvt.rn.bf16.f32 %0, %1;" : "=h"(h1) : "f"(v.y));
    float r0 = v.x - __uint_as_float((uint32_t)h0 << 16);
    float r1 = v.y - __uint_as_float((uint32_t)h1 << 16);
    asm("cvt.rn.bf16.f32 %0, %1;" : "=h"(l0) : "f"(r0));
    asm("cvt.rn.bf16.f32 %0, %1;" : "=h"(l1) : "f"(r1));
    lo_pack = (uint32_t)l0 | ((uint32_t)l1 << 16);
    return (uint32_t)h0 | ((uint32_t)h1 << 16);
}
__device__ __forceinline__ void mma_bf16(
    float& c0, float& c1, float& c2, float& c3,
    uint32_t a0, uint32_t a1, uint32_t a2, uint32_t a3,
    uint32_t b0, uint32_t b1)
{
    asm("mma.sync.aligned.m16n8k16.row.col.f32.bf16.bf16.f32 "
        "{%0,%1,%2,%3}, {%4,%5,%6,%7}, {%8,%9}, {%0,%1,%2,%3};"
        : "+f"(c0), "+f"(c1), "+f"(c2), "+f"(c3)
        : "r"(a0), "r"(a1), "r"(a2), "r"(a3), "r"(b0), "r"(b1));
}
__device__ __forceinline__ uint32_t prmt(uint32_t a, uint32_t b, uint32_t s) {
    uint32_t d;
    asm("prmt.b32 %0, %1, %2, %3;" : "=r"(d) : "r"(a), "r"(b), "r"(s));
    return d;
}
// CTA-scope wait: tx-completion on our own mbarrier orders the async-delivered
// data in our own smem; no cluster-scope fence (no L1 IVALL).
__device__ __forceinline__ void mbar_wait(uint32_t mbar, uint32_t parity) {
    uint32_t done;
    asm volatile(
        "{\n\t.reg .pred p;\n\t"
        "mbarrier.try_wait.parity.acquire.cta.shared::cta.b64 p, [%1], %2;\n\t"
        "selp.b32 %0, 1, 0, p;\n\t}"
        : "=r"(done) : "r"(mbar), "r"(parity) : "memory");
    while (!done) {
        asm volatile(
            "{\n\t.reg .pred p;\n\t"
            "mbarrier.try_wait.parity.acquire.cta.shared::cta.b64 p, [%1], %2, 0x989680;\n\t"
            "selp.b32 %0, 1, 0, p;\n\t}"
            : "=r"(done) : "r"(mbar), "r"(parity) : "memory");
    }
}

__global__ void __cluster_dims__(8, 1, 1) __launch_bounds__(REC_THREADS, 1)
gru_rec(const float* __restrict__ att, const int* __restrict__ lengths,
        const float* __restrict__ W_hh, const float* __restrict__ b_hh,
        const float* __restrict__ b_ih, float* __restrict__ out)
{
    __shared__ uint32_t hx[2][HXW];       // [buf][b*264 + pair*2 + sel]
    __shared__ float ghp[4][4][104];      // [kc][batch][row 0..95, pad 104]
    __shared__ alignas(8) unsigned long long mbar[2];

    uint32_t rank;
    asm("mov.u32 %0, %%cluster_ctarank;" : "=r"(rank));
    const int cid = blockIdx.x >> 3;
    const int b0  = cid * 4;

    const int tid  = threadIdx.x;
    const int warp = tid >> 5;
    const int lane = tid & 31;
    const int m    = warp >> 2;           // m-tile 0..5
    const int kc   = warp & 3;            // k slice 0..3
    const int q    = lane & 3;
    const int rg2  = lane >> 2;           // 0..7

    // ---- loop-invariant A fragments (W_hh hi/lo) ----
    const int row0 = m * 16 + rg2;                               // local row
    const int grow = (row0 >> 5) * 256 + (int)rank * 32 + (row0 & 31);
    uint32_t ahi[4][4], alo[4][4];
#pragma unroll
    for (int ks = 0; ks < 4; ks++) {
        const int k0 = kc * 64 + ks * 16 + q * 2;
        float2 v00 = *(const float2*)&W_hh[(size_t)grow * H_ + k0];
        float2 v10 = *(const float2*)&W_hh[(size_t)(grow + 8) * H_ + k0];
        float2 v01 = *(const float2*)&W_hh[(size_t)grow * H_ + k0 + 8];
        float2 v11 = *(const float2*)&W_hh[(size_t)(grow + 8) * H_ + k0 + 8];
        ahi[ks][0] = split_pack(v00, alo[ks][0]);
        ahi[ks][1] = split_pack(v10, alo[ks][1]);
        ahi[ks][2] = split_pack(v01, alo[ks][2]);
        ahi[ks][3] = split_pack(v11, alo[ks][3]);
    }

    // ---- zero h buffer 0, init mbarriers ----
    for (int i = tid; i < HXW; i += REC_THREADS) hx[0][i] = 0u;
    if (tid < 2) {
        uint32_t mb = (uint32_t)__cvta_generic_to_shared(&mbar[tid]);
        asm volatile("mbarrier.init.shared.b64 [%0], 1;" :: "r"(mb) : "memory");
    }

    // ---- gate constants (threads 0..127: gb = tid>>5, gj = tid&31) ----
    const int gb   = tid >> 5;
    const int gj   = tid & 31;
    const int col  = (int)rank * 32 + gj;
    const int myb  = b0 + gb;
    float bcr = 0.f, bcz = 0.f, bcn = 0.f, bhn = 0.f;
    int mylen = 0;
    if (tid < 128) {
        bcr = b_ih[col] + b_hh[col];
        bcz = b_ih[256 + col] + b_hh[256 + col];
        bcn = b_ih[512 + col];
        bhn = b_hh[512 + col];
        mylen = lengths[myb];
    }
    float hreg = 0.f;
    const int Tmax = max(max(__ldg(&lengths[b0]),     __ldg(&lengths[b0 + 1])),
                         max(__ldg(&lengths[b0 + 2]), __ldg(&lengths[b0 + 3])));

    // ---- lane constants for B-fragment loads ----
    const int wb = (lane >> 3) * 264 + kc * 64 + q * 2 + ((lane >> 2) & 1);

    // ---- hoisted peer addresses (sending lanes: tid<128, even gj) ----
    // rh0[d] = peer-d address of our hx[0] slot; buffer/mbar variants are
    // constant intra-CTA deltas (mapa is an address-bit remap).
    uint32_t rh0[8];
    int32_t  dmb = 0;
    {
        const int pair = (int)rank * 16 + (gj >> 1);
        uint32_t lh0 = (uint32_t)__cvta_generic_to_shared(&hx[0][gb * 264 + pair * 2]);
        uint32_t lm0 = (uint32_t)__cvta_generic_to_shared(&mbar[0]);
        dmb = (int32_t)(lm0 - lh0);
#pragma unroll
        for (int d = 0; d < 8; d++)
            asm("mapa.shared::cluster.u32 %0, %1, %2;"
                : "=r"(rh0[d]) : "r"(lh0), "r"(d));
    }

    __syncthreads();
    asm volatile("barrier.cluster.arrive.aligned;" ::: "memory");
    asm volatile("barrier.cluster.wait.aligned;" ::: "memory");

    uint32_t ph0 = 0, ph1 = 0;

    for (int t = 0; t < Tmax; t++) {
        const int cur = t & 1, nxt = cur ^ 1;

        // arm next buffer (non-gate warp)
        if (tid == 256) {
            uint32_t mn = (uint32_t)__cvta_generic_to_shared(&mbar[nxt]);
            asm volatile("mbarrier.arrive.expect_tx.shared.b64 _, [%0], %1;"
                         :: "r"(mn), "n"(EXP_TX) : "memory");
        }

        // gi prefetch + bias fold (no h dependency)
        float gir = 0.f, giz = 0.f, gin = 0.f, wt = 0.f;
        if (tid < 128) {
            const size_t base = ((size_t)t * B_ + myb) * G3_;
            gir = __ldg(&g_Gi[base + col]) + bcr;
            giz = __ldg(&g_Gi[base + 256 + col]) + bcz;
            gin = __ldg(&g_Gi[base + 512 + col]) + bcn;
            wt  = __ldg(&att[(size_t)myb * T_ + t]);
        }

        if (t > 0) {
            uint32_t mc = (uint32_t)__cvta_generic_to_shared(&mbar[cur]);
            mbar_wait(mc, cur ? ph1 : ph0);
            if (cur) ph1 ^= 1; else ph0 ^= 1;
        }

        // ---- HMMA matvec: 2 passes (Whi, Wlo) over B = [4b x {hh,hl}] ----
        float c0 = 0.f, c1 = 0.f, c2 = 0.f, c3 = 0.f;
        {
            const uint32_t* hxc = hx[cur];
#pragma unroll
            for (int ks = 0; ks < 4; ks++) {
                const uint32_t bf0 = hxc[wb + ks * 16];
                const uint32_t bf1 = hxc[wb + ks * 16 + 8];
                mma_bf16(c0, c1, c2, c3,
                         ahi[ks][0], ahi[ks][1], ahi[ks][2], ahi[ks][3], bf0, bf1);
                mma_bf16(c0, c1, c2, c3,
                         alo[ks][0], alo[ks][1], alo[ks][2], alo[ks][3], bf0, bf1);
            }
        }
        ghp[kc][q][m * 16 + rg2]     = c0 + c1;
        ghp[kc][q][m * 16 + 8 + rg2] = c2 + c3;
        __syncthreads();

        // ---- gates (threads 0..127) + split/pack/send ----
        if (tid < 128) {
            float sr_ = 0.f, sz_ = 0.f, sn_ = 0.f;
#pragma unroll
            for (int k = 0; k < 4; k++) {
                sr_ += ghp[k][gb][gj];
                sz_ += ghp[k][gb][32 + gj];
                sn_ += ghp[k][gb][64 + gj];
            }
            const float hprev = hreg;
            const float r = sigm(gir + sr_);
            const float z = sigm(giz + sz_);
            const float n = tanh_fast(gin + r * (sn_ + bhn));
            const float hnew = (1.f - z) * n + z * hprev;
            const float hg   = wt * hnew + (1.f - wt) * hprev;
            const float hv   = (t < mylen) ? hg : hprev;
            hreg = hv;

            // split hv -> {hh, hl} bf16, pack with neighbor column
            uint16_t hh16, hl16;
            asm("cvt.rn.bf16.f32 %0, %1;" : "=h"(hh16) : "f"(hv));
            const float hlr = hv - __uint_as_float((uint32_t)hh16 << 16);
            asm("cvt.rn.bf16.f32 %0, %1;" : "=h"(hl16) : "f"(hlr));
            const uint32_t own = (uint32_t)hh16 | ((uint32_t)hl16 << 16);
            const uint32_t oth = __shfl_down_sync(0xffffffffu, own, 1);
            if ((gj & 1) == 0) {
                const uint32_t hh2 = prmt(own, oth, 0x5410u);
                const uint32_t hl2 = prmt(own, oth, 0x7632u);
                unsigned long long pk;
                asm("mov.b64 %0, {%1, %2};" : "=l"(pk) : "r"(hh2), "r"(hl2));
                const uint32_t bofs = (uint32_t)nxt * (HXW * 4u);
                const uint32_t mofs = (uint32_t)dmb + (uint32_t)nxt * 8u;
#pragma unroll
                for (int d = 0; d < 8; d++) {
                    const uint32_t rh = rh0[d] + bofs;
                    const uint32_t rm = rh0[d] + mofs;
                    asm volatile(
                        "st.async.shared::cluster.mbarrier::complete_tx::bytes.b64 "
                        "[%0], %1, [%2];"
                        :: "r"(rh), "l"(pk), "r"(rm) : "memory");
                }
            }
        }
    }

    // drain final phase before exit
    {
        uint32_t mf = (uint32_t)__cvta_generic_to_shared(&mbar[Tmax & 1]);
        mbar_wait(mf, (Tmax & 1) ? ph1 : ph0);
    }
    if (tid < 128) out[(size_t)myb * H_ + col] = hreg;

    asm volatile("barrier.cluster.arrive.aligned;" ::: "memory");
    asm volatile("barrier.cluster.wait.aligned;" ::: "memory");
}

// ======================= launch =======================
extern "C" void kernel_launch(void* const* d_in, const int* in_sizes, int n_in,
                              void* d_out, int out_size)
{
    const float* x       = (const float*)d_in[0];
    const float* att     = (const float*)d_in[1];
    const int*   lengths = (const int*)  d_in[2];
    const float* W_ih    = (const float*)d_in[3];
    const float* W_hh    = (const float*)d_in[4];
    const float* b_ih    = (const float*)d_in[5];
    const float* b_hh    = (const float*)d_in[6];
    float* out = (float*)d_out;
    (void)in_sizes; (void)n_in; (void)out_size;

    dim3 ggrid(1024, 12);
    gi_gemm_wmma<<<ggrid, 256>>>(x, W_ih, lengths);
    gru_rec<<<128, REC_THREADS>>>(att, lengths, W_hh, b_hh, b_ih, out);
}

// round 13
// speedup vs baseline: 2.7765x; 1.0114x over previous
#include <cuda_runtime.h>
#include <cuda_bf16.h>
#include <mma.h>
#include <cstdint>

using namespace nvcuda;

#define B_  64
#define T_  2048
#define I_  256
#define H_  256
#define G3_ 768

// 402 MB scratch for precomputed input gates (NO bias): layout [t][b][768]
__device__ float g_Gi[(size_t)B_ * T_ * G3_];

// ======================= Phase 1: Gi = x @ W_ih^T  (wmma bf16 hi/lo) ==========
// (unchanged from R9 — measured ~460 us, rel_err contribution ~4e-6)

#define GBK 32
#define GLD 48

__global__ __launch_bounds__(256) void gi_gemm_wmma(
    const float* __restrict__ x, const float* __restrict__ W_ih,
    const int* __restrict__ lengths)
{
    const int mt    = blockIdx.x;
    const int batch = mt >> 4;
    const int t0    = (mt & 15) * 128;
    if (t0 >= __ldg(&lengths[batch])) return;
    const int n0 = blockIdx.y * 64;

    __shared__ __nv_bfloat16 Ah[128][GLD], Al[128][GLD];
    __shared__ __nv_bfloat16 Bh[64][GLD],  Bl[64][GLD];

    const int tid  = threadIdx.x;
    const int warp = tid >> 5;
    const int wm   = warp >> 1;
    const int wn   = warp & 1;

    wmma::fragment<wmma::accumulator, 16, 16, 16, float> acc[2][2];
#pragma unroll
    for (int mi = 0; mi < 2; mi++)
#pragma unroll
        for (int ni = 0; ni < 2; ni++) wmma::fill_fragment(acc[mi][ni], 0.f);

    for (int ks = 0; ks < I_; ks += GBK) {
#pragma unroll
        for (int j = 0; j < 4; j++) {
            const int idx = tid + j * 256;
            const int row = idx >> 3, c = (idx & 7) * 4;
            float4 v = *(const float4*)&x[(size_t)(batch * T_ + t0 + row) * I_ + ks + c];
            __nv_bfloat16 hx = __float2bfloat16(v.x);
            __nv_bfloat16 hy = __float2bfloat16(v.y);
            __nv_bfloat16 hz = __float2bfloat16(v.z);
            __nv_bfloat16 hw = __float2bfloat16(v.w);
            *(__nv_bfloat162*)&Ah[row][c]     = __nv_bfloat162(hx, hy);
            *(__nv_bfloat162*)&Ah[row][c + 2] = __nv_bfloat162(hz, hw);
            *(__nv_bfloat162*)&Al[row][c] = __nv_bfloat162(
                __float2bfloat16(v.x - __bfloat162float(hx)),
                __float2bfloat16(v.y - __bfloat162float(hy)));
            *(__nv_bfloat162*)&Al[row][c + 2] = __nv_bfloat162(
                __float2bfloat16(v.z - __bfloat162float(hz)),
                __float2bfloat16(v.w - __bfloat162float(hw)));
        }
#pragma unroll
        for (int j = 0; j < 2; j++) {
            const int idx = tid + j * 256;
            const int row = idx >> 3, c = (idx & 7) * 4;
            float4 v = *(const float4*)&W_ih[(size_t)(n0 + row) * I_ + ks + c];
            __nv_bfloat16 hx = __float2bfloat16(v.x);
            __nv_bfloat16 hy = __float2bfloat16(v.y);
            __nv_bfloat16 hz = __float2bfloat16(v.z);
            __nv_bfloat16 hw = __float2bfloat16(v.w);
            *(__nv_bfloat162*)&Bh[row][c]     = __nv_bfloat162(hx, hy);
            *(__nv_bfloat162*)&Bh[row][c + 2] = __nv_bfloat162(hz, hw);
            *(__nv_bfloat162*)&Bl[row][c] = __nv_bfloat162(
                __float2bfloat16(v.x - __bfloat162float(hx)),
                __float2bfloat16(v.y - __bfloat162float(hy)));
            *(__nv_bfloat162*)&Bl[row][c + 2] = __nv_bfloat162(
                __float2bfloat16(v.z - __bfloat162float(hz)),
                __float2bfloat16(v.w - __bfloat162float(hw)));
        }
        __syncthreads();

#pragma unroll
        for (int kk = 0; kk < GBK; kk += 16) {
            wmma::fragment<wmma::matrix_a, 16, 16, 16, __nv_bfloat16,
                           wmma::row_major> ah[2], al[2];
            wmma::fragment<wmma::matrix_b, 16, 16, 16, __nv_bfloat16,
                           wmma::col_major> bh[2], bl[2];
#pragma unroll
            for (int mi = 0; mi < 2; mi++) {
                wmma::load_matrix_sync(ah[mi], &Ah[wm * 32 + mi * 16][kk], GLD);
                wmma::load_matrix_sync(al[mi], &Al[wm * 32 + mi * 16][kk], GLD);
            }
#pragma unroll
            for (int ni = 0; ni < 2; ni++) {
                wmma::load_matrix_sync(bh[ni], &Bh[wn * 32 + ni * 16][kk], GLD);
                wmma::load_matrix_sync(bl[ni], &Bl[wn * 32 + ni * 16][kk], GLD);
            }
#pragma unroll
            for (int mi = 0; mi < 2; mi++)
#pragma unroll
                for (int ni = 0; ni < 2; ni++) {
                    wmma::mma_sync(acc[mi][ni], ah[mi], bh[ni], acc[mi][ni]);
                    wmma::mma_sync(acc[mi][ni], ah[mi], bl[ni], acc[mi][ni]);
                    wmma::mma_sync(acc[mi][ni], al[mi], bh[ni], acc[mi][ni]);
                }
        }
        __syncthreads();
    }

#pragma unroll
    for (int mi = 0; mi < 2; mi++)
#pragma unroll
        for (int ni = 0; ni < 2; ni++) {
            float* dst = &g_Gi[((size_t)(t0 + wm * 32 + mi * 16) * B_ + batch) * G3_
                               + n0 + wn * 32 + ni * 16];
            wmma::store_matrix_sync(dst, acc[mi][ni], (unsigned)(B_ * G3_),
                                    wmma::mem_row_major);
        }
}

// ======================= Phase 2: recurrence (HMMA matvec) ====================
// R11 structure. R12/R13 changes:
//  (a) dual HMMA accumulator chains (hi->c, lo->d): dep depth 8 -> 4
//  (b) split in-loop barrier: matvec-only warps bar.arrive, gate warps
//      bar.sync (safe: ghp overwrite at t+1 is gated by the phase mbar,
//      which requires the gates' sends, which follow their ghp reads)
//  (c) batched ghp reduce loads before any FADD

#define REC_THREADS 768
#define EXP_TX 4096
#define HXW 1056                         // 4 batches * 264 words

__device__ __forceinline__ float sigm(float v) { return 1.f / (1.f + __expf(-v)); }
__device__ __forceinline__ float tanh_fast(float u) {
    const float t = __expf(-2.f * fabsf(u));
    const float m = (1.f - t) / (1.f + t);
    return copysignf(m, u);
}
__device__ __forceinline__ uint32_t split_pack(float2 v, uint32_t& lo_pack) {
    uint16_t h0, h1, l0, l1;
    asm("cvt.rn.bf16.f32 %0, %1;" : "=h"(h0) : "f"(v.x));
    asm("cvt.rn.bf16.f32 %0, %1;" : "=h"(h1) : "f"(v.y));
    float r0 = v.x - __uint_as_float((uint32_t)h0 << 16);
    float r1 = v.y - __uint_as_float((uint32_t)h1 << 16);
    asm("cvt.rn.bf16.f32 %0, %1;" : "=h"(l0) : "f"(r0));
    asm("cvt.rn.bf16.f32 %0, %1;" : "=h"(l1) : "f"(r1));
    lo_pack = (uint32_t)l0 | ((uint32_t)l1 << 16);
    return (uint32_t)h0 | ((uint32_t)h1 << 16);
}
__device__ __forceinline__ void mma_bf16(
    float& c0, float& c1, float& c2, float& c3,
    uint32_t a0, uint32_t a1, uint32_t a2, uint32_t a3,
    uint32_t b0, uint32_t b1)
{
    asm("mma.sync.aligned.m16n8k16.row.col.f32.bf16.bf16.f32 "
        "{%0,%1,%2,%3}, {%4,%5,%6,%7}, {%8,%9}, {%0,%1,%2,%3};"
        : "+f"(c0), "+f"(c1), "+f"(c2), "+f"(c3)
        : "r"(a0), "r"(a1), "r"(a2), "r"(a3), "r"(b0), "r"(b1));
}
__device__ __forceinline__ uint32_t prmt(uint32_t a, uint32_t b, uint32_t s) {
    uint32_t d;
    asm("prmt.b32 %0, %1, %2, %3;" : "=r"(d) : "r"(a), "r"(b), "r"(s));
    return d;
}
__device__ __forceinline__ void mbar_wait(uint32_t mbar, uint32_t parity) {
    uint32_t done;
    asm volatile(
        "{\n\t.reg .pred p;\n\t"
        "mbarrier.try_wait.parity.acquire.cta.shared::cta.b64 p, [%1], %2;\n\t"
        "selp.b32 %0, 1, 0, p;\n\t}"
        : "=r"(done) : "r"(mbar), "r"(parity) : "memory");
    while (!done) {
        asm volatile(
            "{\n\t.reg .pred p;\n\t"
            "mbarrier.try_wait.parity.acquire.cta.shared::cta.b64 p, [%1], %2, 0x989680;\n\t"
            "selp.b32 %0, 1, 0, p;\n\t}"
            : "=r"(done) : "r"(mbar), "r"(parity) : "memory");
    }
}

__global__ void __cluster_dims__(8, 1, 1) __launch_bounds__(REC_THREADS, 1)
gru_rec(const float* __restrict__ att, const int* __restrict__ lengths,
        const float* __restrict__ W_hh, const float* __restrict__ b_hh,
        const float* __restrict__ b_ih, float* __restrict__ out)
{
    __shared__ uint32_t hx[2][HXW];       // [buf][b*264 + pair*2 + sel]
    __shared__ float ghp[4][4][104];      // [kc][batch][row 0..95, pad 104]
    __shared__ alignas(8) unsigned long long mbar[2];

    uint32_t rank;
    asm("mov.u32 %0, %%cluster_ctarank;" : "=r"(rank));
    const int cid = blockIdx.x >> 3;
    const int b0  = cid * 4;

    const int tid  = threadIdx.x;
    const int warp = tid >> 5;
    const int lane = tid & 31;
    const int m    = warp >> 2;           // m-tile 0..5
    const int kc   = warp & 3;            // k slice 0..3
    const int q    = lane & 3;
    const int rg2  = lane >> 2;           // 0..7

    // ---- loop-invariant A fragments (W_hh hi/lo) ----
    const int row0 = m * 16 + rg2;                               // local row
    const int grow = (row0 >> 5) * 256 + (int)rank * 32 + (row0 & 31);
    uint32_t ahi[4][4], alo[4][4];
#pragma unroll
    for (int ks = 0; ks < 4; ks++) {
        const int k0 = kc * 64 + ks * 16 + q * 2;
        float2 v00 = *(const float2*)&W_hh[(size_t)grow * H_ + k0];
        float2 v10 = *(const float2*)&W_hh[(size_t)(grow + 8) * H_ + k0];
        float2 v01 = *(const float2*)&W_hh[(size_t)grow * H_ + k0 + 8];
        float2 v11 = *(const float2*)&W_hh[(size_t)(grow + 8) * H_ + k0 + 8];
        ahi[ks][0] = split_pack(v00, alo[ks][0]);
        ahi[ks][1] = split_pack(v10, alo[ks][1]);
        ahi[ks][2] = split_pack(v01, alo[ks][2]);
        ahi[ks][3] = split_pack(v11, alo[ks][3]);
    }

    // ---- zero h buffer 0, init mbarriers ----
    for (int i = tid; i < HXW; i += REC_THREADS) hx[0][i] = 0u;
    if (tid < 2) {
        uint32_t mb = (uint32_t)__cvta_generic_to_shared(&mbar[tid]);
        asm volatile("mbarrier.init.shared.b64 [%0], 1;" :: "r"(mb) : "memory");
    }

    // ---- gate constants (threads 0..127: gb = tid>>5, gj = tid&31) ----
    const int gb   = tid >> 5;
    const int gj   = tid & 31;
    const int col  = (int)rank * 32 + gj;
    const int myb  = b0 + gb;
    float bcr = 0.f, bcz = 0.f, bcn = 0.f, bhn = 0.f;
    int mylen = 0;
    if (tid < 128) {
        bcr = b_ih[col] + b_hh[col];
        bcz = b_ih[256 + col] + b_hh[256 + col];
        bcn = b_ih[512 + col];
        bhn = b_hh[512 + col];
        mylen = lengths[myb];
    }
    float hreg = 0.f;
    const int Tmax = max(max(__ldg(&lengths[b0]),     __ldg(&lengths[b0 + 1])),
                         max(__ldg(&lengths[b0 + 2]), __ldg(&lengths[b0 + 3])));

    // ---- lane constants for B-fragment loads ----
    const int wb = (lane >> 3) * 264 + kc * 64 + q * 2 + ((lane >> 2) & 1);

    // ---- hoisted peer addresses (sending lanes: tid<128, even gj) ----
    uint32_t rh0[8];
    int32_t  dmb = 0;
    {
        const int pair = (int)rank * 16 + (gj >> 1);
        uint32_t lh0 = (uint32_t)__cvta_generic_to_shared(&hx[0][gb * 264 + pair * 2]);
        uint32_t lm0 = (uint32_t)__cvta_generic_to_shared(&mbar[0]);
        dmb = (int32_t)(lm0 - lh0);
#pragma unroll
        for (int d = 0; d < 8; d++)
            asm("mapa.shared::cluster.u32 %0, %1, %2;"
                : "=r"(rh0[d]) : "r"(lh0), "r"(d));
    }

    __syncthreads();
    asm volatile("barrier.cluster.arrive.aligned;" ::: "memory");
    asm volatile("barrier.cluster.wait.aligned;" ::: "memory");

    uint32_t ph0 = 0, ph1 = 0;

    for (int t = 0; t < Tmax; t++) {
        const int cur = t & 1, nxt = cur ^ 1;

        // arm next buffer (non-gate warp)
        if (tid == 256) {
            uint32_t mn = (uint32_t)__cvta_generic_to_shared(&mbar[nxt]);
            asm volatile("mbarrier.arrive.expect_tx.shared.b64 _, [%0], %1;"
                         :: "r"(mn), "n"(EXP_TX) : "memory");
        }

        // gi prefetch + bias fold (no h dependency)
        float gir = 0.f, giz = 0.f, gin = 0.f, wt = 0.f;
        if (tid < 128) {
            const size_t base = ((size_t)t * B_ + myb) * G3_;
            gir = __ldg(&g_Gi[base + col]) + bcr;
            giz = __ldg(&g_Gi[base + 256 + col]) + bcz;
            gin = __ldg(&g_Gi[base + 512 + col]) + bcn;
            wt  = __ldg(&att[(size_t)myb * T_ + t]);
        }

        if (t > 0) {
            uint32_t mc = (uint32_t)__cvta_generic_to_shared(&mbar[cur]);
            mbar_wait(mc, cur ? ph1 : ph0);
            if (cur) ph1 ^= 1; else ph0 ^= 1;
        }

        // ---- HMMA matvec: dual independent chains (hi->c, lo->d) ----
        float c0 = 0.f, c1 = 0.f, c2 = 0.f, c3 = 0.f;
        float d0 = 0.f, d1 = 0.f, d2 = 0.f, d3 = 0.f;
        {
            const uint32_t* hxc = hx[cur];
#pragma unroll
            for (int ks = 0; ks < 4; ks++) {
                const uint32_t bf0 = hxc[wb + ks * 16];
                const uint32_t bf1 = hxc[wb + ks * 16 + 8];
                mma_bf16(c0, c1, c2, c3,
                         ahi[ks][0], ahi[ks][1], ahi[ks][2], ahi[ks][3], bf0, bf1);
                mma_bf16(d0, d1, d2, d3,
                         alo[ks][0], alo[ks][1], alo[ks][2], alo[ks][3], bf0, bf1);
            }
        }
        ghp[kc][q][m * 16 + rg2]     = (c0 + d0) + (c1 + d1);
        ghp[kc][q][m * 16 + 8 + rg2] = (c2 + d2) + (c3 + d3);

        // split barrier: matvec-only warps just arrive; gate warps sync
        if (tid >= 128) {
            asm volatile("bar.arrive 1, %0;" :: "n"(REC_THREADS) : "memory");
        } else {
            asm volatile("bar.sync 1, %0;" :: "n"(REC_THREADS) : "memory");

            // ---- gates (threads 0..127): batched reduce, gate math, send ----
            float pr[4], pz[4], pn[4];
#pragma unroll
            for (int k = 0; k < 4; k++) pr[k] = ghp[k][gb][gj];
#pragma unroll
            for (int k = 0; k < 4; k++) pz[k] = ghp[k][gb][32 + gj];
#pragma unroll
            for (int k = 0; k < 4; k++) pn[k] = ghp[k][gb][64 + gj];
            const float sr_ = (pr[0] + pr[1]) + (pr[2] + pr[3]);
            const float sz_ = (pz[0] + pz[1]) + (pz[2] + pz[3]);
            const float sn_ = (pn[0] + pn[1]) + (pn[2] + pn[3]);

            const float hprev = hreg;
            const float r = sigm(gir + sr_);
            const float z = sigm(giz + sz_);
            const float n = tanh_fast(gin + r * (sn_ + bhn));
            const float hnew = (1.f - z) * n + z * hprev;
            const float hg   = wt * hnew + (1.f - wt) * hprev;
            const float hv   = (t < mylen) ? hg : hprev;
            hreg = hv;

            // split hv -> {hh, hl} bf16, pack with neighbor column
            uint16_t hh16, hl16;
            asm("cvt.rn.bf16.f32 %0, %1;" : "=h"(hh16) : "f"(hv));
            const float hlr = hv - __uint_as_float((uint32_t)hh16 << 16);
            asm("cvt.rn.bf16.f32 %0, %1;" : "=h"(hl16) : "f"(hlr));
            const uint32_t own = (uint32_t)hh16 | ((uint32_t)hl16 << 16);
            const uint32_t oth = __shfl_down_sync(0xffffffffu, own, 1);
            if ((gj & 1) == 0) {
                const uint32_t hh2 = prmt(own, oth, 0x5410u);
                const uint32_t hl2 = prmt(own, oth, 0x7632u);
                unsigned long long pk;
                asm("mov.b64 %0, {%1, %2};" : "=l"(pk) : "r"(hh2), "r"(hl2));
                const uint32_t bofs = (uint32_t)nxt * (HXW * 4u);
                const uint32_t mofs = (uint32_t)dmb + (uint32_t)nxt * 8u;
#pragma unroll
                for (int d = 0; d < 8; d++) {
                    const uint32_t rh = rh0[d] + bofs;
                    const uint32_t rm = rh0[d] + mofs;
                    asm volatile(
                        "st.async.shared::cluster.mbarrier::complete_tx::bytes.b64 "
                        "[%0], %1, [%2];"
                        :: "r"(rh), "l"(pk), "r"(rm) : "memory");
                }
            }
        }
    }

    // drain final phase before exit
    {
        uint32_t mf = (uint32_t)__cvta_generic_to_shared(&mbar[Tmax & 1]);
        mbar_wait(mf, (Tmax & 1) ? ph1 : ph0);
    }
    if (tid < 128) out[(size_t)myb * H_ + col] = hreg;

    asm volatile("barrier.cluster.arrive.aligned;" ::: "memory");
    asm volatile("barrier.cluster.wait.aligned;" ::: "memory");
}

// ======================= launch =======================
extern "C" void kernel_launch(void* const* d_in, const int* in_sizes, int n_in,
                              void* d_out, int out_size)
{
    const float* x       = (const float*)d_in[0];
    const float* att     = (const float*)d_in[1];
    const int*   lengths = (const int*)  d_in[2];
    const float* W_ih    = (const float*)d_in[3];
    const float* W_hh    = (const float*)d_in[4];
    const float* b_ih    = (const float*)d_in[5];
    const float* b_hh    = (const float*)d_in[6];
    float* out = (float*)d_out;
    (void)in_sizes; (void)n_in; (void)out_size;

    dim3 ggrid(1024, 12);
    gi_gemm_wmma<<<ggrid, 256>>>(x, W_ih, lengths);
    gru_rec<<<128, REC_THREADS>>>(att, lengths, W_hh, b_hh, b_ih, out);
}